// round 2
// baseline (speedup 1.0000x reference)
#include <cuda_runtime.h>

// rate_RNN_mante: T=1000, B=64, I=4, H=1024, O=2, P=16
// Low-rank recurrence exploited: r @ Wr^T = (r @ pout) @ (l*pin)^T
// One persistent CTA per batch element; mem state in registers.
// (Resubmission of R1 kernel — prior round died to container infra, no kernel evidence.)

#define T_STEPS 1000
#define BATCH   64
#define I_DIM   4
#define H_DIM   1024
#define O_DIM   2
#define P_DIM   16
#define HPT     4                 // h-rows per thread
#define NTHREADS 256              // H_DIM / HPT
#define NWARPS  (NTHREADS / 32)
#define NRED    18                // 16 z-values + 2 y-values fused in one reduction

__global__ __launch_bounds__(NTHREADS, 1)
void rate_rnn_kernel(const float* __restrict__ x,     // (T,B,I,1)
                     const float* __restrict__ Win,   // (H,I)
                     const float* __restrict__ Wout,  // (O,H)
                     const float* __restrict__ pin,   // (H,P)
                     const float* __restrict__ pout,  // (H,P)
                     const float* __restrict__ l,     // (P,)
                     float* __restrict__ y)           // (T,B,O,1)
{
    const int b    = blockIdx.x;
    const int tid  = threadIdx.x;
    const int lane = tid & 31;
    const int warp = tid >> 5;

    __shared__ float pbuf[NWARPS][NRED];  // per-warp partials
    __shared__ float zbuf[P_DIM];         // broadcast z

    // ---- load per-thread constants into registers ----
    float lvec[P_DIM];
    #pragma unroll
    for (int p = 0; p < P_DIM; p++) lvec[p] = l[p];

    float mem[HPT];
    float win[HPT][I_DIM];
    float m[HPT][NRED];    // [pout (16) | Wout^T (2)] per h
    float lp[HPT][P_DIM];  // l * pin per h

    #pragma unroll
    for (int k = 0; k < HPT; k++) {
        const int h = tid + k * NTHREADS;
        mem[k] = 0.0f;
        #pragma unroll
        for (int i = 0; i < I_DIM; i++) win[k][i] = Win[h * I_DIM + i];
        #pragma unroll
        for (int p = 0; p < P_DIM; p++) {
            m[k][p]  = pout[h * P_DIM + p];
            lp[k][p] = lvec[p] * pin[h * P_DIM + p];
        }
        m[k][16] = Wout[h];           // Wout[0][h]
        m[k][17] = Wout[H_DIM + h];   // Wout[1][h]
    }

    const float lm = 0.95122942450071400910f;  // exp(-DT/TAUM) = exp(-0.05)
    const float om = 1.0f - lm;

    // x[t,b,:] = 4 contiguous floats at ((t*B)+b)*4  -> one float4 per step
    const float4* xp = reinterpret_cast<const float4*>(x) + b;
    float4 xc = __ldg(xp);   // t = 0
    float4 xn = xc;

    // Loop t = 0..T inclusive.  Iteration t computes r_t = tanh(mem_t),
    // stores y[t-1] = Wout . r_t (reference: y[t] uses tanh(mem_{t+1})),
    // and (for t < T) advances mem via the low-rank feedback.
    for (int t = 0; t <= T_STEPS; t++) {
        // software prefetch next step's input (hides DRAM latency)
        if (t < T_STEPS - 1) xn = __ldg(xp + (t + 1) * BATCH);

        // ---- phase 1: tanh + local accumulation + warp reduce ----
        float part[NRED];
        #pragma unroll
        for (int j = 0; j < NRED; j++) part[j] = 0.0f;

        #pragma unroll
        for (int k = 0; k < HPT; k++) {
            const float r = tanhf(mem[k]);
            #pragma unroll
            for (int j = 0; j < NRED; j++)
                part[j] = fmaf(r, m[k][j], part[j]);
        }

        #pragma unroll
        for (int off = 16; off > 0; off >>= 1) {
            #pragma unroll
            for (int j = 0; j < NRED; j++)
                part[j] += __shfl_xor_sync(0xffffffffu, part[j], off);
        }
        if (lane == 0) {
            #pragma unroll
            for (int j = 0; j < NRED; j++) pbuf[warp][j] = part[j];
        }
        __syncthreads();

        // ---- phase 2: cross-warp reduce; z -> smem, y -> global ----
        if (tid < NRED) {
            float s = 0.0f;
            #pragma unroll
            for (int w = 0; w < NWARPS; w++) s += pbuf[w][tid];
            if (tid < P_DIM) {
                zbuf[tid] = s;
            } else if (t > 0) {
                y[((t - 1) * BATCH + b) * O_DIM + (tid - P_DIM)] = s;
            }
        }
        __syncthreads();

        if (t == T_STEPS) break;

        // ---- phase 3: feedback + leaky integration ----
        float z[P_DIM];
        #pragma unroll
        for (int p = 0; p < P_DIM; p++) z[p] = zbuf[p];

        #pragma unroll
        for (int k = 0; k < HPT; k++) {
            float It = win[k][0] * xc.x;
            It = fmaf(win[k][1], xc.y, It);
            It = fmaf(win[k][2], xc.z, It);
            It = fmaf(win[k][3], xc.w, It);
            #pragma unroll
            for (int p = 0; p < P_DIM; p++)
                It = fmaf(z[p], lp[k][p], It);
            mem[k] = fmaf(lm, mem[k], om * It);
        }
        xc = xn;
    }
}

extern "C" void kernel_launch(void* const* d_in, const int* in_sizes, int n_in,
                              void* d_out, int out_size)
{
    const float* x    = (const float*)d_in[0];
    const float* Win  = (const float*)d_in[1];
    const float* Wout = (const float*)d_in[2];
    const float* pin  = (const float*)d_in[3];
    const float* pout = (const float*)d_in[4];
    const float* l    = (const float*)d_in[5];
    float* y = (float*)d_out;

    rate_rnn_kernel<<<BATCH, NTHREADS>>>(x, Win, Wout, pin, pout, l, y);
}

// round 5
// speedup vs baseline: 1.7518x; 1.7518x over previous
#include <cuda_runtime.h>

// rate_RNN_mante: T=1000, B=64, I=4, H=1024, O=2, P=16
// Low-rank recurrence: r @ Wr^T = (r @ pout) @ (l*pin)^T
// One persistent CTA per batch element; mem state in registers.
// R5 = R4 resubmission (infra failure, kernel never ran):
// tanh.approx + split-butterfly warp reduction (value-halving) + vectorized staging.

#define T_STEPS 1000
#define BATCH   64
#define I_DIM   4
#define H_DIM   1024
#define O_DIM   2
#define P_DIM   16
#define HPT     4                 // h-rows per thread
#define NTHREADS 256              // H_DIM / HPT
#define NWARPS  (NTHREADS / 32)
#define NRED    18                // 16 z-values + 2 y-values
#define PROW    20                // pbuf row stride (floats), conflict-free columns

__device__ __forceinline__ float fast_tanh(float x) {
    float r;
    asm("tanh.approx.f32 %0, %1;" : "=f"(r) : "f"(x));
    return r;
}

__device__ __forceinline__ float shfl_xor_f(float v, int off) {
    return __shfl_xor_sync(0xffffffffu, v, off);
}

__global__ __launch_bounds__(NTHREADS, 1)
void rate_rnn_kernel(const float* __restrict__ x,     // (T,B,I,1)
                     const float* __restrict__ Win,   // (H,I)
                     const float* __restrict__ Wout,  // (O,H)
                     const float* __restrict__ pin,   // (H,P)
                     const float* __restrict__ pout,  // (H,P)
                     const float* __restrict__ l,     // (P,)
                     float* __restrict__ y)           // (T,B,O,1)
{
    const int b    = blockIdx.x;
    const int tid  = threadIdx.x;
    const int lane = tid & 31;
    const int warp = tid >> 5;

    __shared__ __align__(16) float pbuf[NWARPS][PROW];  // per-warp reduced values
    __shared__ __align__(16) float zbuf[P_DIM];         // broadcast z

    const float lm = 0.95122942450071400910f;  // exp(-DT/TAUM) = exp(-0.05)
    const float om = 1.0f - lm;

    // split-butterfly lane roles (computed once)
    const bool hi16 = (lane & 16) != 0;
    const bool hi8  = (lane & 8)  != 0;
    const bool hi4  = (lane & 4)  != 0;
    const bool hi2  = (lane & 2)  != 0;
    const bool wz   = (lane & 1)  == 0;           // z writer lanes
    const int  zj   = (lane >> 1) & 15;           // z index this lane-pair owns
    const bool wy   = (lane & 15) == 0;           // y writer lanes (0 and 16)
    const int  yj   = 16 + (lane >> 4);           // y index

    float lvec[P_DIM];
    #pragma unroll
    for (int p = 0; p < P_DIM; p++) lvec[p] = l[p];

    float mem[HPT];
    float win[HPT][I_DIM];     // om * Win
    float m[HPT][NRED];        // [pout (16) | Wout^T (2)]
    float lp[HPT][P_DIM];      // om * l * pin

    #pragma unroll
    for (int k = 0; k < HPT; k++) {
        const int h = tid + k * NTHREADS;
        mem[k] = 0.0f;
        #pragma unroll
        for (int i = 0; i < I_DIM; i++) win[k][i] = om * Win[h * I_DIM + i];
        #pragma unroll
        for (int p = 0; p < P_DIM; p++) {
            m[k][p]  = pout[h * P_DIM + p];
            lp[k][p] = om * lvec[p] * pin[h * P_DIM + p];
        }
        m[k][16] = Wout[h];           // Wout[0][h]
        m[k][17] = Wout[H_DIM + h];   // Wout[1][h]
    }

    const float4* xp = reinterpret_cast<const float4*>(x) + b;
    float4 xc = __ldg(xp);   // t = 0
    float4 xn = xc;

    // Iteration t: r_t = tanh(mem_t); y[t-1] = Wout.r_t; advance mem (t < T).
    for (int t = 0; t <= T_STEPS; t++) {
        {   // branchless clamped prefetch of next x
            int tn = t + 1; if (tn > T_STEPS - 1) tn = T_STEPS - 1;
            xn = __ldg(xp + tn * BATCH);
        }

        // ---- phase 1: tanh + local accumulation ----
        float part[NRED];
        #pragma unroll
        for (int j = 0; j < NRED; j++) part[j] = 0.0f;

        #pragma unroll
        for (int k = 0; k < HPT; k++) {
            const float r = fast_tanh(mem[k]);
            #pragma unroll
            for (int j = 0; j < NRED; j++)
                part[j] = fmaf(r, m[k][j], part[j]);
        }

        // ---- split-butterfly: 16 z values, halving live set each round ----
        float v8[8];
        #pragma unroll
        for (int i = 0; i < 8; i++) {
            float send = hi16 ? part[i] : part[i + 8];
            float keep = hi16 ? part[i + 8] : part[i];
            v8[i] = keep + shfl_xor_f(send, 16);
        }
        float v4[4];
        #pragma unroll
        for (int i = 0; i < 4; i++) {
            float send = hi8 ? v8[i] : v8[i + 4];
            float keep = hi8 ? v8[i + 4] : v8[i];
            v4[i] = keep + shfl_xor_f(send, 8);
        }
        float v2[2];
        #pragma unroll
        for (int i = 0; i < 2; i++) {
            float send = hi4 ? v4[i] : v4[i + 2];
            float keep = hi4 ? v4[i + 2] : v4[i];
            v2[i] = keep + shfl_xor_f(send, 4);
        }
        float v1;
        {
            float send = hi2 ? v2[0] : v2[1];
            float keep = hi2 ? v2[1] : v2[0];
            v1 = keep + shfl_xor_f(send, 2);
        }
        v1 += shfl_xor_f(v1, 1);   // lane pair holds z[zj]

        // ---- y values: split once (16), then naive 4 rounds on 1 value ----
        float wv;
        {
            float send = hi16 ? part[16] : part[17];
            float keep = hi16 ? part[17] : part[16];
            wv = keep + shfl_xor_f(send, 16);
        }
        wv += shfl_xor_f(wv, 8);
        wv += shfl_xor_f(wv, 4);
        wv += shfl_xor_f(wv, 2);
        wv += shfl_xor_f(wv, 1);   // all lanes: y[yj] partial for this warp

        if (wz) pbuf[warp][zj] = v1;
        if (wy) pbuf[warp][yj] = wv;
        __syncthreads();

        // ---- phase 2: cross-warp reduce; z -> smem, y -> global ----
        if (tid < NRED) {
            float s = pbuf[0][tid];
            #pragma unroll
            for (int w = 1; w < NWARPS; w++) s += pbuf[w][tid];
            if (tid < P_DIM) {
                zbuf[tid] = s;
            } else if (t > 0) {
                y[((t - 1) * BATCH + b) * O_DIM + (tid - P_DIM)] = s;
            }
        }
        __syncthreads();

        if (t == T_STEPS) break;

        // ---- phase 3: feedback + leaky integration (3-way tree per h) ----
        const float4* zv = reinterpret_cast<const float4*>(zbuf);
        const float4 z0 = zv[0], z1 = zv[1], z2 = zv[2], z3 = zv[3];

        #pragma unroll
        for (int k = 0; k < HPT; k++) {
            float a0 = lm * mem[k];
            a0 = fmaf(win[k][0], xc.x, a0);
            a0 = fmaf(win[k][1], xc.y, a0);
            a0 = fmaf(win[k][2], xc.z, a0);
            a0 = fmaf(win[k][3], xc.w, a0);

            float a1 = z0.x * lp[k][0];
            a1 = fmaf(z0.y, lp[k][1],  a1);
            a1 = fmaf(z0.z, lp[k][2],  a1);
            a1 = fmaf(z0.w, lp[k][3],  a1);
            a1 = fmaf(z1.x, lp[k][4],  a1);
            a1 = fmaf(z1.y, lp[k][5],  a1);
            a1 = fmaf(z1.z, lp[k][6],  a1);
            a1 = fmaf(z1.w, lp[k][7],  a1);

            float a2 = z2.x * lp[k][8];
            a2 = fmaf(z2.y, lp[k][9],  a2);
            a2 = fmaf(z2.z, lp[k][10], a2);
            a2 = fmaf(z2.w, lp[k][11], a2);
            a2 = fmaf(z3.x, lp[k][12], a2);
            a2 = fmaf(z3.y, lp[k][13], a2);
            a2 = fmaf(z3.z, lp[k][14], a2);
            a2 = fmaf(z3.w, lp[k][15], a2);

            mem[k] = a0 + a1 + a2;
        }
        xc = xn;
    }
}

extern "C" void kernel_launch(void* const* d_in, const int* in_sizes, int n_in,
                              void* d_out, int out_size)
{
    const float* x    = (const float*)d_in[0];
    const float* Win  = (const float*)d_in[1];
    const float* Wout = (const float*)d_in[2];
    const float* pin  = (const float*)d_in[3];
    const float* pout = (const float*)d_in[4];
    const float* l    = (const float*)d_in[5];
    float* y = (float*)d_out;

    rate_rnn_kernel<<<BATCH, NTHREADS>>>(x, Win, Wout, pin, pout, l, y);
}